// round 2
// baseline (speedup 1.0000x reference)
#include <cuda_runtime.h>
#include <cmath>

// Problem constants
#define T_TOK 32768
#define D_MOD 256
#define FFN_N 1024
#define P_N 8

// Scratch (device globals are the sanctioned way to get scratch; no allocs)
__device__ float g_fused[(size_t)T_TOK * FFN_N];  // 128 MB
__device__ float g_sgate[FFN_N];

// ---------------- packed f32x2 helpers (Blackwell FADD2/FFMA2) ----------------
__device__ __forceinline__ unsigned long long f2pack(float lo, float hi) {
    unsigned long long r;
    asm("mov.b64 %0, {%1,%2};" : "=l"(r) : "f"(lo), "f"(hi));
    return r;
}
__device__ __forceinline__ void f2unpack(unsigned long long v, float& lo, float& hi) {
    asm("mov.b64 {%0,%1}, %2;" : "=f"(lo), "=f"(hi) : "l"(v));
}
__device__ __forceinline__ void fma2(unsigned long long& d, unsigned long long a, unsigned long long b) {
    asm("fma.rn.f32x2 %0, %1, %2, %0;" : "+l"(d) : "l"(a), "l"(b));
}
__device__ __forceinline__ unsigned long long add2(unsigned long long a, unsigned long long b) {
    unsigned long long d;
    asm("add.rn.f32x2 %0, %1, %2;" : "=l"(d) : "l"(a), "l"(b));
    return d;
}

// ---------------- K0: s = sigmoid(alpha), 1024 values ----------------
__global__ void k_sgate(const float* __restrict__ alpha) {
    int j = threadIdx.x;
    g_sgate[j] = 1.0f / (1.0f + expf(-alpha[j]));
}

// ---------------- K1: fused[i,j] = g*trop + (1-g)*gelu(x@Wc+bc) ----------------
// Tile: 64 tokens x 64 ffn, BK=32, 256 threads, 4x4 microtile.
__global__ __launch_bounds__(256, 2) void k_stage1(
    const float* __restrict__ x,    // [T, 256]
    const float* __restrict__ Wt,   // [1024, 256]
    const float* __restrict__ bt,   // [1024]
    const float* __restrict__ slc,  // sl_cvx [1024, 8]
    const float* __restrict__ ofc,  // of_cvx
    const float* __restrict__ slv,  // sl_ccv
    const float* __restrict__ ofv,  // of_ccv
    const float* __restrict__ Wc,   // [256, 1024]
    const float* __restrict__ bc,   // [1024]
    const float* __restrict__ Wg,   // [256, 1024]
    const float* __restrict__ bg)   // [1024]
{
    __shared__ float xs[32][64];   // xs[k][i]
    __shared__ float wts[32][64];  // wts[k][j]
    __shared__ float wcs[32][64];  // wcs[k][j]
    __shared__ float wgs[32][64];  // wgs[k][j]

    const int tid = threadIdx.x;
    const int tx = tid & 15;
    const int ty = tid >> 4;
    const int i0 = blockIdx.x * 64;
    const int j0 = blockIdx.y * 64;

    float m[4][4];
#pragma unroll
    for (int a = 0; a < 4; ++a)
#pragma unroll
        for (int b = 0; b < 4; ++b) m[a][b] = -3.402823466e38f;
    unsigned long long ca[4][2], ga[4][2];
#pragma unroll
    for (int a = 0; a < 4; ++a) { ca[a][0] = ca[a][1] = 0ULL; ga[a][0] = ga[a][1] = 0ULL; }

    for (int kc = 0; kc < 256; kc += 32) {
        // ---- cooperative loads ----
#pragma unroll
        for (int it = 0; it < 2; ++it) {
            int idx = tid + it * 256;              // 0..511
            int r  = idx >> 3;                      // 0..63 (token row / wt row)
            int k4 = (idx & 7) << 2;                // 0,4,..,28
            float4 v = *reinterpret_cast<const float4*>(x + (i0 + r) * 256 + kc + k4);
            xs[k4 + 0][r] = v.x; xs[k4 + 1][r] = v.y; xs[k4 + 2][r] = v.z; xs[k4 + 3][r] = v.w;
            float4 w = *reinterpret_cast<const float4*>(Wt + (j0 + r) * 256 + kc + k4);
            wts[k4 + 0][r] = w.x; wts[k4 + 1][r] = w.y; wts[k4 + 2][r] = w.z; wts[k4 + 3][r] = w.w;

            int kk = idx >> 4;                      // 0..31
            int j4 = (idx & 15) << 2;               // 0,4,..,60
            float4 c4 = *reinterpret_cast<const float4*>(Wc + (kc + kk) * 1024 + j0 + j4);
            *reinterpret_cast<float4*>(&wcs[kk][j4]) = c4;
            float4 g4 = *reinterpret_cast<const float4*>(Wg + (kc + kk) * 1024 + j0 + j4);
            *reinterpret_cast<float4*>(&wgs[kk][j4]) = g4;
        }
        __syncthreads();

        // ---- inner product ----
#pragma unroll 8
        for (int k = 0; k < 32; ++k) {
            float4 xv = *reinterpret_cast<const float4*>(&xs[k][ty << 2]);
            ulonglong2 wtv = *reinterpret_cast<const ulonglong2*>(&wts[k][tx << 2]);
            ulonglong2 wcv = *reinterpret_cast<const ulonglong2*>(&wcs[k][tx << 2]);
            ulonglong2 wgv = *reinterpret_cast<const ulonglong2*>(&wgs[k][tx << 2]);
            float xf[4] = {xv.x, xv.y, xv.z, xv.w};
#pragma unroll
            for (int a = 0; a < 4; ++a) {
                unsigned long long xp = f2pack(xf[a], xf[a]);
                {
                    unsigned long long t2 = add2(xp, wtv.x);
                    float lo, hi; f2unpack(t2, lo, hi);
                    m[a][0] = fmaxf(m[a][0], lo);
                    m[a][1] = fmaxf(m[a][1], hi);
                    fma2(ca[a][0], xp, wcv.x);
                    fma2(ga[a][0], xp, wgv.x);
                }
                {
                    unsigned long long t2 = add2(xp, wtv.y);
                    float lo, hi; f2unpack(t2, lo, hi);
                    m[a][2] = fmaxf(m[a][2], lo);
                    m[a][3] = fmaxf(m[a][3], hi);
                    fma2(ca[a][1], xp, wcv.y);
                    fma2(ga[a][1], xp, wgv.y);
                }
            }
        }
        __syncthreads();
    }

    // ---- epilogue ----
    float cs[4][4], gs[4][4];
#pragma unroll
    for (int a = 0; a < 4; ++a) {
        f2unpack(ca[a][0], cs[a][0], cs[a][1]);
        f2unpack(ca[a][1], cs[a][2], cs[a][3]);
        f2unpack(ga[a][0], gs[a][0], gs[a][1]);
        f2unpack(ga[a][1], gs[a][2], gs[a][3]);
    }

    float res[4][4];
#pragma unroll
    for (int b = 0; b < 4; ++b) {
        int j = j0 + (tx << 2) + b;
        float btj = bt[j];
        float sj  = g_sgate[j];
        float bcj = bc[j];
        float bgj = bg[j];
        float4 s0 = *reinterpret_cast<const float4*>(slc + j * 8);
        float4 s1 = *reinterpret_cast<const float4*>(slc + j * 8 + 4);
        float4 o0 = *reinterpret_cast<const float4*>(ofc + j * 8);
        float4 o1 = *reinterpret_cast<const float4*>(ofc + j * 8 + 4);
        float4 v0 = *reinterpret_cast<const float4*>(slv + j * 8);
        float4 v1 = *reinterpret_cast<const float4*>(slv + j * 8 + 4);
        float4 w0 = *reinterpret_cast<const float4*>(ofv + j * 8);
        float4 w1 = *reinterpret_cast<const float4*>(ofv + j * 8 + 4);
#pragma unroll
        for (int a = 0; a < 4; ++a) {
            float t = m[a][b] + btj;
            float cvx = fmaf(t, s0.x, o0.x);
            cvx = fmaxf(cvx, fmaf(t, s0.y, o0.y));
            cvx = fmaxf(cvx, fmaf(t, s0.z, o0.z));
            cvx = fmaxf(cvx, fmaf(t, s0.w, o0.w));
            cvx = fmaxf(cvx, fmaf(t, s1.x, o1.x));
            cvx = fmaxf(cvx, fmaf(t, s1.y, o1.y));
            cvx = fmaxf(cvx, fmaf(t, s1.z, o1.z));
            cvx = fmaxf(cvx, fmaf(t, s1.w, o1.w));
            float ccv = fmaf(t, v0.x, w0.x);
            ccv = fminf(ccv, fmaf(t, v0.y, w0.y));
            ccv = fminf(ccv, fmaf(t, v0.z, w0.z));
            ccv = fminf(ccv, fmaf(t, v0.w, w0.w));
            ccv = fminf(ccv, fmaf(t, v1.x, w1.x));
            ccv = fminf(ccv, fmaf(t, v1.y, w1.y));
            ccv = fminf(ccv, fmaf(t, v1.z, w1.z));
            ccv = fminf(ccv, fmaf(t, v1.w, w1.w));
            float trop = sj * cvx + (1.0f - sj) * ccv;

            float cval = cs[a][b] + bcj;
            float cla = cval * normcdff(cval);  // exact gelu: x * Phi(x)

            float gv = gs[a][b] + bgj;
            float gate = 1.0f / (1.0f + expf(-gv));

            res[a][b] = gate * trop + (1.0f - gate) * cla;
        }
    }
#pragma unroll
    for (int a = 0; a < 4; ++a) {
        float4 st = make_float4(res[a][0], res[a][1], res[a][2], res[a][3]);
        *reinterpret_cast<float4*>(g_fused + (size_t)(i0 + (ty << 2) + a) * 1024 + j0 + (tx << 2)) = st;
    }
}

// ---------------- K2: out = fused @ Wd + bd ----------------
// Tile: 64 x 64, BK=32, 256 threads, 4x4 microtile with FFMA2.
__global__ __launch_bounds__(256, 2) void k_out(
    const float* __restrict__ Wd,  // [1024, 256]
    const float* __restrict__ bd,  // [256]
    float* __restrict__ out)       // [T, 256]
{
    __shared__ float fs[32][64];   // fs[k][i]
    __shared__ float wds[32][64];  // wds[k][n]

    const int tid = threadIdx.x;
    const int tx = tid & 15;
    const int ty = tid >> 4;
    const int i0 = blockIdx.x * 64;
    const int n0 = blockIdx.y * 64;

    unsigned long long acc[4][2];
#pragma unroll
    for (int a = 0; a < 4; ++a) { acc[a][0] = 0ULL; acc[a][1] = 0ULL; }

    for (int kc = 0; kc < 1024; kc += 32) {
#pragma unroll
        for (int it = 0; it < 2; ++it) {
            int idx = tid + it * 256;
            int r  = idx >> 3;
            int k4 = (idx & 7) << 2;
            float4 v = *reinterpret_cast<const float4*>(g_fused + (size_t)(i0 + r) * 1024 + kc + k4);
            fs[k4 + 0][r] = v.x; fs[k4 + 1][r] = v.y; fs[k4 + 2][r] = v.z; fs[k4 + 3][r] = v.w;

            int kk = idx >> 4;
            int j4 = (idx & 15) << 2;
            float4 w = *reinterpret_cast<const float4*>(Wd + (kc + kk) * 256 + n0 + j4);
            *reinterpret_cast<float4*>(&wds[kk][j4]) = w;
        }
        __syncthreads();

#pragma unroll 8
        for (int k = 0; k < 32; ++k) {
            float4 fv = *reinterpret_cast<const float4*>(&fs[k][ty << 2]);
            ulonglong2 wv = *reinterpret_cast<const ulonglong2*>(&wds[k][tx << 2]);
            float ff[4] = {fv.x, fv.y, fv.z, fv.w};
#pragma unroll
            for (int a = 0; a < 4; ++a) {
                unsigned long long xp = f2pack(ff[a], ff[a]);
                fma2(acc[a][0], xp, wv.x);
                fma2(acc[a][1], xp, wv.y);
            }
        }
        __syncthreads();
    }

    float4 bdv = *reinterpret_cast<const float4*>(bd + n0 + (tx << 2));
#pragma unroll
    for (int a = 0; a < 4; ++a) {
        float r0, r1, r2, r3;
        f2unpack(acc[a][0], r0, r1);
        f2unpack(acc[a][1], r2, r3);
        float4 st = make_float4(r0 + bdv.x, r1 + bdv.y, r2 + bdv.z, r3 + bdv.w);
        *reinterpret_cast<float4*>(out + (size_t)(i0 + (ty << 2) + a) * 256 + n0 + (tx << 2)) = st;
    }
}

extern "C" void kernel_launch(void* const* d_in, const int* in_sizes, int n_in,
                              void* d_out, int out_size) {
    const float* x     = (const float*)d_in[0];
    const float* Wt    = (const float*)d_in[1];
    const float* bt    = (const float*)d_in[2];
    const float* slc   = (const float*)d_in[3];
    const float* ofc   = (const float*)d_in[4];
    const float* slv   = (const float*)d_in[5];
    const float* ofv   = (const float*)d_in[6];
    const float* alpha = (const float*)d_in[7];
    const float* Wc    = (const float*)d_in[8];
    const float* bc    = (const float*)d_in[9];
    const float* Wg    = (const float*)d_in[10];
    const float* bg    = (const float*)d_in[11];
    const float* Wd    = (const float*)d_in[12];
    const float* bd    = (const float*)d_in[13];
    float* out = (float*)d_out;

    k_sgate<<<1, 1024>>>(alpha);

    dim3 g1(T_TOK / 64, FFN_N / 64);
    k_stage1<<<g1, 256>>>(x, Wt, bt, slc, ofc, slv, ofv, Wc, bc, Wg, bg);

    dim3 g2(T_TOK / 64, D_MOD / 64);
    k_out<<<g2, 256>>>(Wd, bd, out);
}

// round 4
// speedup vs baseline: 1.1757x; 1.1757x over previous
#include <cuda_runtime.h>
#include <cuda_bf16.h>
#include <cstdint>
#include <cmath>

#define T_TOK 32768
#define D_MOD 256
#define FFN_N 1024

// ---------------- scratch (device globals; no allocs allowed) ----------------
__device__ float g_trop[(size_t)T_TOK * FFN_N];          // 134 MB
__device__ float g_sgate[FFN_N];
__device__ __nv_bfloat16 g_xh[(size_t)T_TOK * D_MOD];
__device__ __nv_bfloat16 g_xl[(size_t)T_TOK * D_MOD];
__device__ __nv_bfloat16 g_wch[FFN_N * D_MOD];           // Wc^T hi [j][d]
__device__ __nv_bfloat16 g_wcl[FFN_N * D_MOD];
__device__ __nv_bfloat16 g_wgh[FFN_N * D_MOD];
__device__ __nv_bfloat16 g_wgl[FFN_N * D_MOD];
__device__ __nv_bfloat16 g_wdh[D_MOD * FFN_N];           // Wd^T hi [n][k]
__device__ __nv_bfloat16 g_wdl[D_MOD * FFN_N];
__device__ __nv_bfloat16 g_fh[(size_t)T_TOK * FFN_N];    // fused hi
__device__ __nv_bfloat16 g_fl[(size_t)T_TOK * FFN_N];    // fused lo

// ---------------- helpers ----------------
__device__ __forceinline__ uint32_t smem_u32(const void* p) {
    uint32_t a;
    asm("{ .reg .u64 t; cvta.to.shared.u64 t, %1; cvt.u32.u64 %0, t; }" : "=r"(a) : "l"(p));
    return a;
}
__device__ __forceinline__ uint32_t swz(uint32_t off) { return off ^ ((off >> 3) & 0x70); }

__device__ __forceinline__ void ldm_x4(uint32_t* r, uint32_t addr) {
    asm volatile("ldmatrix.sync.aligned.m8n8.x4.shared.b16 {%0,%1,%2,%3}, [%4];"
                 : "=r"(r[0]), "=r"(r[1]), "=r"(r[2]), "=r"(r[3]) : "r"(addr));
}
__device__ __forceinline__ void mma16816(float* c, const uint32_t* a, uint32_t b0, uint32_t b1) {
    asm volatile("mma.sync.aligned.m16n8k16.row.col.f32.bf16.bf16.f32 "
                 "{%0,%1,%2,%3}, {%4,%5,%6,%7}, {%8,%9}, {%0,%1,%2,%3};"
                 : "+f"(c[0]), "+f"(c[1]), "+f"(c[2]), "+f"(c[3])
                 : "r"(a[0]), "r"(a[1]), "r"(a[2]), "r"(a[3]), "r"(b0), "r"(b1));
}

// ---------------- K0: s = sigmoid(alpha) ----------------
__global__ void k_sgate(const float* __restrict__ alpha) {
    int j = threadIdx.x;
    g_sgate[j] = 1.0f / (1.0f + expf(-alpha[j]));
}

// ---------------- split x -> bf16 hi/lo ----------------
__global__ void k_split_x(const float* __restrict__ x) {
    size_t idx = (size_t)blockIdx.x * 256 + threadIdx.x;   // float4 index
    float4 v = reinterpret_cast<const float4*>(x)[idx];
    float f[4] = {v.x, v.y, v.z, v.w};
    __nv_bfloat16 h[4], l[4];
#pragma unroll
    for (int q = 0; q < 4; ++q) {
        h[q] = __float2bfloat16_rn(f[q]);
        l[q] = __float2bfloat16_rn(f[q] - __bfloat162float(h[q]));
    }
    __nv_bfloat162* ph = reinterpret_cast<__nv_bfloat162*>(g_xh) + idx * 2;
    __nv_bfloat162* pl = reinterpret_cast<__nv_bfloat162*>(g_xl) + idx * 2;
    ph[0] = __nv_bfloat162(h[0], h[1]); ph[1] = __nv_bfloat162(h[2], h[3]);
    pl[0] = __nv_bfloat162(l[0], l[1]); pl[1] = __nv_bfloat162(l[2], l[3]);
}

// ---------------- transpose + split Wc, Wg ----------------
__global__ void k_split_wcg(const float* __restrict__ Wc, const float* __restrict__ Wg) {
    int j = blockIdx.x;
    int d = threadIdx.x;
    float c = Wc[(size_t)d * FFN_N + j];
    __nv_bfloat16 ch = __float2bfloat16_rn(c);
    g_wch[(size_t)j * D_MOD + d] = ch;
    g_wcl[(size_t)j * D_MOD + d] = __float2bfloat16_rn(c - __bfloat162float(ch));
    float g = Wg[(size_t)d * FFN_N + j];
    __nv_bfloat16 gh = __float2bfloat16_rn(g);
    g_wgh[(size_t)j * D_MOD + d] = gh;
    g_wgl[(size_t)j * D_MOD + d] = __float2bfloat16_rn(g - __bfloat162float(gh));
}

// ---------------- transpose + split Wd ----------------
__global__ void k_split_wd(const float* __restrict__ Wd) {
    int n = blockIdx.x;
    int k = threadIdx.x;
    float w = Wd[(size_t)k * D_MOD + n];
    __nv_bfloat16 wh = __float2bfloat16_rn(w);
    g_wdh[(size_t)n * FFN_N + k] = wh;
    g_wdl[(size_t)n * FFN_N + k] = __float2bfloat16_rn(w - __bfloat162float(wh));
}

// ---------------- tropical kernel ----------------
__global__ __launch_bounds__(256, 2) void k_trop(
    const float* __restrict__ x, const float* __restrict__ Wt, const float* __restrict__ bt,
    const float* __restrict__ slc, const float* __restrict__ ofc,
    const float* __restrict__ slv, const float* __restrict__ ofv)
{
    __shared__ float xs[32][64];
    __shared__ float wts[32][64];

    const int tid = threadIdx.x;
    const int tx = tid & 15;
    const int ty = tid >> 4;
    const int i0 = blockIdx.x * 64;
    const int j0 = blockIdx.y * 64;

    float m[4][4];
#pragma unroll
    for (int a = 0; a < 4; ++a)
#pragma unroll
        for (int b = 0; b < 4; ++b) m[a][b] = -3.402823466e38f;

    for (int kc = 0; kc < 256; kc += 32) {
#pragma unroll
        for (int it = 0; it < 2; ++it) {
            int idx = tid + it * 256;
            int r  = idx >> 3;
            int k4 = (idx & 7) << 2;
            float4 v = *reinterpret_cast<const float4*>(x + (size_t)(i0 + r) * 256 + kc + k4);
            xs[k4 + 0][r] = v.x; xs[k4 + 1][r] = v.y; xs[k4 + 2][r] = v.z; xs[k4 + 3][r] = v.w;
            float4 w = *reinterpret_cast<const float4*>(Wt + (size_t)(j0 + r) * 256 + kc + k4);
            wts[k4 + 0][r] = w.x; wts[k4 + 1][r] = w.y; wts[k4 + 2][r] = w.z; wts[k4 + 3][r] = w.w;
        }
        __syncthreads();

#pragma unroll 8
        for (int k = 0; k < 32; ++k) {
            float4 xv = *reinterpret_cast<const float4*>(&xs[k][ty << 2]);
            float4 wv = *reinterpret_cast<const float4*>(&wts[k][tx << 2]);
            float xf[4] = {xv.x, xv.y, xv.z, xv.w};
#pragma unroll
            for (int a = 0; a < 4; ++a) {
                float xa = xf[a];
                m[a][0] = fmaxf(m[a][0], xa + wv.x);
                m[a][1] = fmaxf(m[a][1], xa + wv.y);
                m[a][2] = fmaxf(m[a][2], xa + wv.z);
                m[a][3] = fmaxf(m[a][3], xa + wv.w);
            }
        }
        __syncthreads();
    }

    float res[4][4];
#pragma unroll
    for (int b = 0; b < 4; ++b) {
        int j = j0 + (tx << 2) + b;
        float btj = bt[j];
        float sj  = g_sgate[j];
        float4 s0 = *reinterpret_cast<const float4*>(slc + j * 8);
        float4 s1 = *reinterpret_cast<const float4*>(slc + j * 8 + 4);
        float4 o0 = *reinterpret_cast<const float4*>(ofc + j * 8);
        float4 o1 = *reinterpret_cast<const float4*>(ofc + j * 8 + 4);
        float4 v0 = *reinterpret_cast<const float4*>(slv + j * 8);
        float4 v1 = *reinterpret_cast<const float4*>(slv + j * 8 + 4);
        float4 w0 = *reinterpret_cast<const float4*>(ofv + j * 8);
        float4 w1 = *reinterpret_cast<const float4*>(ofv + j * 8 + 4);
#pragma unroll
        for (int a = 0; a < 4; ++a) {
            float t = m[a][b] + btj;
            float cvx = fmaf(t, s0.x, o0.x);
            cvx = fmaxf(cvx, fmaf(t, s0.y, o0.y));
            cvx = fmaxf(cvx, fmaf(t, s0.z, o0.z));
            cvx = fmaxf(cvx, fmaf(t, s0.w, o0.w));
            cvx = fmaxf(cvx, fmaf(t, s1.x, o1.x));
            cvx = fmaxf(cvx, fmaf(t, s1.y, o1.y));
            cvx = fmaxf(cvx, fmaf(t, s1.z, o1.z));
            cvx = fmaxf(cvx, fmaf(t, s1.w, o1.w));
            float ccv = fmaf(t, v0.x, w0.x);
            ccv = fminf(ccv, fmaf(t, v0.y, w0.y));
            ccv = fminf(ccv, fmaf(t, v0.z, w0.z));
            ccv = fminf(ccv, fmaf(t, v0.w, w0.w));
            ccv = fminf(ccv, fmaf(t, v1.x, w1.x));
            ccv = fminf(ccv, fmaf(t, v1.y, w1.y));
            ccv = fminf(ccv, fmaf(t, v1.z, w1.z));
            ccv = fminf(ccv, fmaf(t, v1.w, w1.w));
            res[a][b] = sj * cvx + (1.0f - sj) * ccv;
        }
    }
#pragma unroll
    for (int a = 0; a < 4; ++a) {
        float4 st = make_float4(res[a][0], res[a][1], res[a][2], res[a][3]);
        *reinterpret_cast<float4*>(g_trop + (size_t)(i0 + (ty << 2) + a) * FFN_N + j0 + (tx << 2)) = st;
    }
}

// ---------------- k_cg: warp-MMA split-bf16  C=x@Wc, G=x@Wg + fused epilogue ----------------
// Block 128(M) x 128(N), 8 warps (2 M x 4 N). Warp tile 64x32. BK=64. 12 stages (3 terms x 4 chunks).
__global__ __launch_bounds__(256, 1) void k_cg(const float* __restrict__ bc, const float* __restrict__ bg) {
    __shared__ __align__(128) __nv_bfloat16 sA[128 * 64];
    __shared__ __align__(128) __nv_bfloat16 sBc[128 * 64];
    __shared__ __align__(128) __nv_bfloat16 sBg[128 * 64];

    const int tid = threadIdx.x;
    const int wid = tid >> 5;
    const int lane = tid & 31;
    const int warp_m = wid >> 2;        // 0..1
    const int warp_n = wid & 3;         // 0..3
    const int i0 = blockIdx.x * 128;
    const int j0 = blockIdx.y * 128;

    const uint32_t saA = smem_u32(sA);
    const uint32_t saBc = smem_u32(sBc);
    const uint32_t saBg = smem_u32(sBg);

    float accC[4][4][4];
    float accG[4][4][4];
#pragma unroll
    for (int mt = 0; mt < 4; ++mt)
#pragma unroll
        for (int nt = 0; nt < 4; ++nt)
#pragma unroll
            for (int q = 0; q < 4; ++q) { accC[mt][nt][q] = 0.0f; accG[mt][nt][q] = 0.0f; }

    // ldmatrix lane addressing (row within 16, k-half select)
    const int lm_row = lane & 15;
    const int lm_kh  = (lane >> 4) * 8;   // 0 or 8 (bf16 cols)

    for (int ch = 0; ch < 12; ++ch) {
        const int term = ch >> 2;
        const int koff = (ch & 3) << 6;
        const __nv_bfloat16* As  = (term == 1) ? g_xl  : g_xh;
        const __nv_bfloat16* Bc_ = (term == 2) ? g_wcl : g_wch;
        const __nv_bfloat16* Bg_ = (term == 2) ? g_wgl : g_wgh;
#pragma unroll
        for (int t = 0; t < 4; ++t) {
            int idx = tid + (t << 8);
            int r = idx >> 3;
            int c8 = (idx & 7) << 3;
            uint32_t so = swz((uint32_t)(r * 128 + (c8 << 1)));
            *reinterpret_cast<uint4*>((char*)sA + so)  = *reinterpret_cast<const uint4*>(As  + (size_t)(i0 + r) * 256 + koff + c8);
            *reinterpret_cast<uint4*>((char*)sBc + so) = *reinterpret_cast<const uint4*>(Bc_ + (size_t)(j0 + r) * 256 + koff + c8);
            *reinterpret_cast<uint4*>((char*)sBg + so) = *reinterpret_cast<const uint4*>(Bg_ + (size_t)(j0 + r) * 256 + koff + c8);
        }
        __syncthreads();

#pragma unroll
        for (int ks = 0; ks < 4; ++ks) {
            uint32_t af[4][4];
#pragma unroll
            for (int mt = 0; mt < 4; ++mt) {
                uint32_t off = swz((uint32_t)((warp_m * 64 + mt * 16 + lm_row) * 128 + (ks * 16 + lm_kh) * 2));
                ldm_x4(af[mt], saA + off);
            }
            uint32_t bcf[2][4], bgf[2][4];
#pragma unroll
            for (int nt2 = 0; nt2 < 2; ++nt2) {
                uint32_t off = swz((uint32_t)((warp_n * 32 + nt2 * 16 + lm_row) * 128 + (ks * 16 + lm_kh) * 2));
                ldm_x4(bcf[nt2], saBc + off);
                ldm_x4(bgf[nt2], saBg + off);
            }
#pragma unroll
            for (int mt = 0; mt < 4; ++mt)
#pragma unroll
                for (int nt = 0; nt < 4; ++nt) {
                    int g2 = nt >> 1, sb = nt & 1;
                    mma16816(accC[mt][nt], af[mt], bcf[g2][sb], bcf[g2][sb + 2]);
                    mma16816(accG[mt][nt], af[mt], bgf[g2][sb], bgf[g2][sb + 2]);
                }
        }
        __syncthreads();
    }

    // epilogue: fused = g*trop + (1-g)*gelu(C+bc), split to bf16 hi/lo
#pragma unroll
    for (int mt = 0; mt < 4; ++mt) {
#pragma unroll
        for (int nt = 0; nt < 4; ++nt) {
#pragma unroll
            for (int half = 0; half < 2; ++half) {   // rows (lane>>2) and +8
                int i = i0 + warp_m * 64 + mt * 16 + (lane >> 2) + 8 * half;
                int j = j0 + warp_n * 32 + nt * 8 + (lane & 3) * 2;
                float c0v = accC[mt][nt][half * 2 + 0];
                float c1v = accC[mt][nt][half * 2 + 1];
                float g0v = accG[mt][nt][half * 2 + 0];
                float g1v = accG[mt][nt][half * 2 + 1];
                float2 t2 = *reinterpret_cast<const float2*>(g_trop + (size_t)i * FFN_N + j);

                float cval0 = c0v + bc[j],     cval1 = c1v + bc[j + 1];
                float cla0 = cval0 * normcdff(cval0);
                float cla1 = cval1 * normcdff(cval1);
                float gv0 = g0v + bg[j],       gv1 = g1v + bg[j + 1];
                float gate0 = 1.0f / (1.0f + expf(-gv0));
                float gate1 = 1.0f / (1.0f + expf(-gv1));
                float f0 = gate0 * t2.x + (1.0f - gate0) * cla0;
                float f1 = gate1 * t2.y + (1.0f - gate1) * cla1;

                __nv_bfloat16 h0 = __float2bfloat16_rn(f0);
                __nv_bfloat16 h1 = __float2bfloat16_rn(f1);
                __nv_bfloat16 l0 = __float2bfloat16_rn(f0 - __bfloat162float(h0));
                __nv_bfloat16 l1 = __float2bfloat16_rn(f1 - __bfloat162float(h1));
                *reinterpret_cast<__nv_bfloat162*>(g_fh + (size_t)i * FFN_N + j) = __nv_bfloat162(h0, h1);
                *reinterpret_cast<__nv_bfloat162*>(g_fl + (size_t)i * FFN_N + j) = __nv_bfloat162(l0, l1);
            }
        }
    }
}

// ---------------- k_d: warp-MMA split-bf16  out = fused @ Wd + bd ----------------
// Block 128(M) x 128(N), 8 warps (2x4), BK=64, 48 stages (3 terms x 16 chunks).
__global__ __launch_bounds__(256, 2) void k_d(const float* __restrict__ bd, float* __restrict__ out) {
    __shared__ __align__(128) __nv_bfloat16 sA[128 * 64];
    __shared__ __align__(128) __nv_bfloat16 sB[128 * 64];

    const int tid = threadIdx.x;
    const int wid = tid >> 5;
    const int lane = tid & 31;
    const int warp_m = wid >> 2;
    const int warp_n = wid & 3;
    const int i0 = blockIdx.x * 128;
    const int n0 = blockIdx.y * 128;

    const uint32_t saA = smem_u32(sA);
    const uint32_t saB = smem_u32(sB);

    float acc[4][4][4];
#pragma unroll
    for (int mt = 0; mt < 4; ++mt)
#pragma unroll
        for (int nt = 0; nt < 4; ++nt)
#pragma unroll
            for (int q = 0; q < 4; ++q) acc[mt][nt][q] = 0.0f;

    const int lm_row = lane & 15;
    const int lm_kh  = (lane >> 4) * 8;

    for (int ch = 0; ch < 48; ++ch) {
        const int term = ch >> 4;
        const int koff = (ch & 15) << 6;
        const __nv_bfloat16* As = (term == 1) ? g_fl  : g_fh;
        const __nv_bfloat16* Bs = (term == 2) ? g_wdl : g_wdh;
#pragma unroll
        for (int t = 0; t < 4; ++t) {
            int idx = tid + (t << 8);
            int r = idx >> 3;
            int c8 = (idx & 7) << 3;
            uint32_t so = swz((uint32_t)(r * 128 + (c8 << 1)));
            *reinterpret_cast<uint4*>((char*)sA + so) = *reinterpret_cast<const uint4*>(As + (size_t)(i0 + r) * FFN_N + koff + c8);
            *reinterpret_cast<uint4*>((char*)sB + so) = *reinterpret_cast<const uint4*>(Bs + (size_t)(n0 + r) * FFN_N + koff + c8);
        }
        __syncthreads();

#pragma unroll
        for (int ks = 0; ks < 4; ++ks) {
            uint32_t af[4][4];
#pragma unroll
            for (int mt = 0; mt < 4; ++mt) {
                uint32_t off = swz((uint32_t)((warp_m * 64 + mt * 16 + lm_row) * 128 + (ks * 16 + lm_kh) * 2));
                ldm_x4(af[mt], saA + off);
            }
            uint32_t bf[2][4];
#pragma unroll
            for (int nt2 = 0; nt2 < 2; ++nt2) {
                uint32_t off = swz((uint32_t)((warp_n * 32 + nt2 * 16 + lm_row) * 128 + (ks * 16 + lm_kh) * 2));
                ldm_x4(bf[nt2], saB + off);
            }
#pragma unroll
            for (int mt = 0; mt < 4; ++mt)
#pragma unroll
                for (int nt = 0; nt < 4; ++nt) {
                    int g2 = nt >> 1, sb = nt & 1;
                    mma16816(acc[mt][nt], af[mt], bf[g2][sb], bf[g2][sb + 2]);
                }
        }
        __syncthreads();
    }

#pragma unroll
    for (int mt = 0; mt < 4; ++mt)
#pragma unroll
        for (int nt = 0; nt < 4; ++nt)
#pragma unroll
            for (int half = 0; half < 2; ++half) {
                int i = i0 + warp_m * 64 + mt * 16 + (lane >> 2) + 8 * half;
                int n = n0 + warp_n * 32 + nt * 8 + (lane & 3) * 2;
                float o0 = acc[mt][nt][half * 2 + 0] + bd[n];
                float o1 = acc[mt][nt][half * 2 + 1] + bd[n + 1];
                *reinterpret_cast<float2*>(out + (size_t)i * D_MOD + n) = make_float2(o0, o1);
            }
}

// ---------------- launch ----------------
extern "C" void kernel_launch(void* const* d_in, const int* in_sizes, int n_in,
                              void* d_out, int out_size) {
    const float* x     = (const float*)d_in[0];
    const float* Wt    = (const float*)d_in[1];
    const float* bt    = (const float*)d_in[2];
    const float* slc   = (const float*)d_in[3];
    const float* ofc   = (const float*)d_in[4];
    const float* slv   = (const float*)d_in[5];
    const float* ofv   = (const float*)d_in[6];
    const float* alpha = (const float*)d_in[7];
    const float* Wc    = (const float*)d_in[8];
    const float* bc    = (const float*)d_in[9];
    const float* Wg    = (const float*)d_in[10];
    const float* bg    = (const float*)d_in[11];
    const float* Wd    = (const float*)d_in[12];
    const float* bd    = (const float*)d_in[13];
    float* out = (float*)d_out;

    k_sgate<<<1, 1024>>>(alpha);
    k_split_x<<<(T_TOK * D_MOD / 4) / 256, 256>>>(x);
    k_split_wcg<<<FFN_N, D_MOD>>>(Wc, Wg);
    k_split_wd<<<D_MOD, FFN_N>>>(Wd);

    dim3 gt(T_TOK / 64, FFN_N / 64);
    k_trop<<<gt, 256>>>(x, Wt, bt, slc, ofc, slv, ofv);

    dim3 gcg(T_TOK / 128, FFN_N / 128);
    k_cg<<<gcg, 256>>>(bc, bg);

    dim3 gd(T_TOK / 128, D_MOD / 128);
    k_d<<<gd, 256>>>(bd, out);
}

// round 5
// speedup vs baseline: 1.3181x; 1.1211x over previous
#include <cuda_runtime.h>
#include <cuda_bf16.h>
#include <cstdint>
#include <cmath>

#define T_TOK 32768
#define D_MOD 256
#define FFN_N 1024

// ---------------- scratch (device globals; no allocs allowed) ----------------
__device__ float g_trop[(size_t)T_TOK * FFN_N];          // 134 MB
__device__ float g_C[(size_t)T_TOK * FFN_N];             // x@Wc (fp32)
__device__ float g_G[(size_t)T_TOK * FFN_N];             // x@Wg (fp32)
__device__ float g_sgate[FFN_N];
__device__ __nv_bfloat16 g_xh[(size_t)T_TOK * D_MOD];
__device__ __nv_bfloat16 g_xl[(size_t)T_TOK * D_MOD];
__device__ __nv_bfloat16 g_wch[FFN_N * D_MOD];           // Wc^T hi [j][d]
__device__ __nv_bfloat16 g_wcl[FFN_N * D_MOD];
__device__ __nv_bfloat16 g_wgh[FFN_N * D_MOD];
__device__ __nv_bfloat16 g_wgl[FFN_N * D_MOD];
__device__ __nv_bfloat16 g_wdh[D_MOD * FFN_N];           // Wd^T hi [n][k]
__device__ __nv_bfloat16 g_wdl[D_MOD * FFN_N];
__device__ __nv_bfloat16 g_fh[(size_t)T_TOK * FFN_N];    // fused hi
__device__ __nv_bfloat16 g_fl[(size_t)T_TOK * FFN_N];    // fused lo

// ---------------- helpers ----------------
__device__ __forceinline__ uint32_t smem_u32(const void* p) {
    uint32_t a;
    asm("{ .reg .u64 t; cvta.to.shared.u64 t, %1; cvt.u32.u64 %0, t; }" : "=r"(a) : "l"(p));
    return a;
}
__device__ __forceinline__ uint32_t swz(uint32_t off) { return off ^ ((off >> 3) & 0x70); }

__device__ __forceinline__ void ldm_x4(uint32_t* r, uint32_t addr) {
    asm volatile("ldmatrix.sync.aligned.m8n8.x4.shared.b16 {%0,%1,%2,%3}, [%4];"
                 : "=r"(r[0]), "=r"(r[1]), "=r"(r[2]), "=r"(r[3]) : "r"(addr));
}
__device__ __forceinline__ void mma16816(float* c, const uint32_t* a, uint32_t b0, uint32_t b1) {
    asm volatile("mma.sync.aligned.m16n8k16.row.col.f32.bf16.bf16.f32 "
                 "{%0,%1,%2,%3}, {%4,%5,%6,%7}, {%8,%9}, {%0,%1,%2,%3};"
                 : "+f"(c[0]), "+f"(c[1]), "+f"(c[2]), "+f"(c[3])
                 : "r"(a[0]), "r"(a[1]), "r"(a[2]), "r"(a[3]), "r"(b0), "r"(b1));
}
__device__ __forceinline__ unsigned long long add2(unsigned long long a, unsigned long long b) {
    unsigned long long d;
    asm("add.rn.f32x2 %0, %1, %2;" : "=l"(d) : "l"(a), "l"(b));
    return d;
}
__device__ __forceinline__ void f2unpack(unsigned long long v, float& lo, float& hi) {
    asm("mov.b64 {%0,%1}, %2;" : "=f"(lo), "=f"(hi) : "l"(v));
}

// ---------------- K0: s = sigmoid(alpha) ----------------
__global__ void k_sgate(const float* __restrict__ alpha) {
    int j = threadIdx.x;
    g_sgate[j] = 1.0f / (1.0f + expf(-alpha[j]));
}

// ---------------- split x -> bf16 hi/lo ----------------
__global__ void k_split_x(const float* __restrict__ x) {
    size_t idx = (size_t)blockIdx.x * 256 + threadIdx.x;
    float4 v = reinterpret_cast<const float4*>(x)[idx];
    float f[4] = {v.x, v.y, v.z, v.w};
    __nv_bfloat16 h[4], l[4];
#pragma unroll
    for (int q = 0; q < 4; ++q) {
        h[q] = __float2bfloat16_rn(f[q]);
        l[q] = __float2bfloat16_rn(f[q] - __bfloat162float(h[q]));
    }
    __nv_bfloat162* ph = reinterpret_cast<__nv_bfloat162*>(g_xh) + idx * 2;
    __nv_bfloat162* pl = reinterpret_cast<__nv_bfloat162*>(g_xl) + idx * 2;
    ph[0] = __nv_bfloat162(h[0], h[1]); ph[1] = __nv_bfloat162(h[2], h[3]);
    pl[0] = __nv_bfloat162(l[0], l[1]); pl[1] = __nv_bfloat162(l[2], l[3]);
}

// ---------------- transpose + split Wc, Wg ----------------
__global__ void k_split_wcg(const float* __restrict__ Wc, const float* __restrict__ Wg) {
    int j = blockIdx.x;
    int d = threadIdx.x;
    float c = Wc[(size_t)d * FFN_N + j];
    __nv_bfloat16 ch = __float2bfloat16_rn(c);
    g_wch[(size_t)j * D_MOD + d] = ch;
    g_wcl[(size_t)j * D_MOD + d] = __float2bfloat16_rn(c - __bfloat162float(ch));
    float g = Wg[(size_t)d * FFN_N + j];
    __nv_bfloat16 gh = __float2bfloat16_rn(g);
    g_wgh[(size_t)j * D_MOD + d] = gh;
    g_wgl[(size_t)j * D_MOD + d] = __float2bfloat16_rn(g - __bfloat162float(gh));
}

// ---------------- transpose + split Wd ----------------
__global__ void k_split_wd(const float* __restrict__ Wd) {
    int n = blockIdx.x;
    int k = threadIdx.x;
    float w = Wd[(size_t)k * D_MOD + n];
    __nv_bfloat16 wh = __float2bfloat16_rn(w);
    g_wdh[(size_t)n * FFN_N + k] = wh;
    g_wdl[(size_t)n * FFN_N + k] = __float2bfloat16_rn(w - __bfloat162float(wh));
}

// ---------------- tropical kernel: k-pair packed (ADD2 + FMNMX3) ----------------
__global__ __launch_bounds__(256, 2) void k_trop(
    const float* __restrict__ x, const float* __restrict__ Wt, const float* __restrict__ bt,
    const float* __restrict__ slc, const float* __restrict__ ofc,
    const float* __restrict__ slv, const float* __restrict__ ofv)
{
    // k-pairs: xs2[k2][i] = (x[i,2k2], x[i,2k2+1]); rows padded to 66 to avoid store conflicts
    __shared__ __align__(16) float2 xs2[16][66];
    __shared__ __align__(16) float2 ws2[16][66];

    const int tid = threadIdx.x;
    const int tx = tid & 15;
    const int ty = tid >> 4;
    const int i0 = blockIdx.x * 64;
    const int j0 = blockIdx.y * 64;

    float m[4][4];
#pragma unroll
    for (int a = 0; a < 4; ++a)
#pragma unroll
        for (int b = 0; b < 4; ++b) m[a][b] = -3.402823466e38f;

    for (int kc = 0; kc < 256; kc += 32) {
#pragma unroll
        for (int it = 0; it < 2; ++it) {
            int idx = tid + it * 256;        // 0..511
            int r  = idx >> 3;               // 0..63
            int k2 = (idx & 7) << 1;         // 0,2,..,14
            float4 v = *reinterpret_cast<const float4*>(x + (size_t)(i0 + r) * 256 + kc + (k2 << 1));
            xs2[k2][r]     = make_float2(v.x, v.y);
            xs2[k2 + 1][r] = make_float2(v.z, v.w);
            float4 w = *reinterpret_cast<const float4*>(Wt + (size_t)(j0 + r) * 256 + kc + (k2 << 1));
            ws2[k2][r]     = make_float2(w.x, w.y);
            ws2[k2 + 1][r] = make_float2(w.z, w.w);
        }
        __syncthreads();

#pragma unroll 4
        for (int k2 = 0; k2 < 16; ++k2) {
            ulonglong2 xa = *reinterpret_cast<const ulonglong2*>(&xs2[k2][ty << 2]);
            ulonglong2 xb = *reinterpret_cast<const ulonglong2*>(&xs2[k2][(ty << 2) + 2]);
            ulonglong2 wa = *reinterpret_cast<const ulonglong2*>(&ws2[k2][tx << 2]);
            ulonglong2 wb = *reinterpret_cast<const ulonglong2*>(&ws2[k2][(tx << 2) + 2]);
            unsigned long long xp[4] = {xa.x, xa.y, xb.x, xb.y};
            unsigned long long wp[4] = {wa.x, wa.y, wb.x, wb.y};
#pragma unroll
            for (int a = 0; a < 4; ++a)
#pragma unroll
                for (int b = 0; b < 4; ++b) {
                    unsigned long long t2 = add2(xp[a], wp[b]);
                    float lo, hi; f2unpack(t2, lo, hi);
                    m[a][b] = fmaxf(m[a][b], fmaxf(lo, hi));   // -> FMNMX3
                }
        }
        __syncthreads();
    }

    float res[4][4];
#pragma unroll
    for (int b = 0; b < 4; ++b) {
        int j = j0 + (tx << 2) + b;
        float btj = bt[j];
        float sj  = g_sgate[j];
        float4 s0 = *reinterpret_cast<const float4*>(slc + j * 8);
        float4 s1 = *reinterpret_cast<const float4*>(slc + j * 8 + 4);
        float4 o0 = *reinterpret_cast<const float4*>(ofc + j * 8);
        float4 o1 = *reinterpret_cast<const float4*>(ofc + j * 8 + 4);
        float4 v0 = *reinterpret_cast<const float4*>(slv + j * 8);
        float4 v1 = *reinterpret_cast<const float4*>(slv + j * 8 + 4);
        float4 w0 = *reinterpret_cast<const float4*>(ofv + j * 8);
        float4 w1 = *reinterpret_cast<const float4*>(ofv + j * 8 + 4);
#pragma unroll
        for (int a = 0; a < 4; ++a) {
            float t = m[a][b] + btj;
            float cvx = fmaf(t, s0.x, o0.x);
            cvx = fmaxf(cvx, fmaf(t, s0.y, o0.y));
            cvx = fmaxf(cvx, fmaf(t, s0.z, o0.z));
            cvx = fmaxf(cvx, fmaf(t, s0.w, o0.w));
            cvx = fmaxf(cvx, fmaf(t, s1.x, o1.x));
            cvx = fmaxf(cvx, fmaf(t, s1.y, o1.y));
            cvx = fmaxf(cvx, fmaf(t, s1.z, o1.z));
            cvx = fmaxf(cvx, fmaf(t, s1.w, o1.w));
            float ccv = fmaf(t, v0.x, w0.x);
            ccv = fminf(ccv, fmaf(t, v0.y, w0.y));
            ccv = fminf(ccv, fmaf(t, v0.z, w0.z));
            ccv = fminf(ccv, fmaf(t, v0.w, w0.w));
            ccv = fminf(ccv, fmaf(t, v1.x, w1.x));
            ccv = fminf(ccv, fmaf(t, v1.y, w1.y));
            ccv = fminf(ccv, fmaf(t, v1.z, w1.z));
            ccv = fminf(ccv, fmaf(t, v1.w, w1.w));
            res[a][b] = sj * cvx + (1.0f - sj) * ccv;
        }
    }
#pragma unroll
    for (int a = 0; a < 4; ++a) {
        float4 st = make_float4(res[a][0], res[a][1], res[a][2], res[a][3]);
        *reinterpret_cast<float4*>(g_trop + (size_t)(i0 + (ty << 2) + a) * FFN_N + j0 + (tx << 2)) = st;
    }
}

// ---------------- k_cg_mma: warp-MMA split-bf16  C=x@Wc, G=x@Wg -> fp32 scratch ----------------
__global__ __launch_bounds__(256, 1) void k_cg_mma() {
    __shared__ __align__(128) __nv_bfloat16 sA[128 * 64];
    __shared__ __align__(128) __nv_bfloat16 sBc[128 * 64];
    __shared__ __align__(128) __nv_bfloat16 sBg[128 * 64];

    const int tid = threadIdx.x;
    const int wid = tid >> 5;
    const int lane = tid & 31;
    const int warp_m = wid >> 2;
    const int warp_n = wid & 3;
    const int i0 = blockIdx.x * 128;
    const int j0 = blockIdx.y * 128;

    const uint32_t saA = smem_u32(sA);
    const uint32_t saBc = smem_u32(sBc);
    const uint32_t saBg = smem_u32(sBg);

    float accC[4][4][4];
    float accG[4][4][4];
#pragma unroll
    for (int mt = 0; mt < 4; ++mt)
#pragma unroll
        for (int nt = 0; nt < 4; ++nt)
#pragma unroll
            for (int q = 0; q < 4; ++q) { accC[mt][nt][q] = 0.0f; accG[mt][nt][q] = 0.0f; }

    const int lm_row = lane & 15;
    const int lm_kh  = (lane >> 4) * 8;

    for (int ch = 0; ch < 12; ++ch) {
        const int term = ch >> 2;
        const int koff = (ch & 3) << 6;
        const __nv_bfloat16* As  = (term == 1) ? g_xl  : g_xh;
        const __nv_bfloat16* Bc_ = (term == 2) ? g_wcl : g_wch;
        const __nv_bfloat16* Bg_ = (term == 2) ? g_wgl : g_wgh;
#pragma unroll
        for (int t = 0; t < 4; ++t) {
            int idx = tid + (t << 8);
            int r = idx >> 3;
            int c8 = (idx & 7) << 3;
            uint32_t so = swz((uint32_t)(r * 128 + (c8 << 1)));
            *reinterpret_cast<uint4*>((char*)sA + so)  = *reinterpret_cast<const uint4*>(As  + (size_t)(i0 + r) * 256 + koff + c8);
            *reinterpret_cast<uint4*>((char*)sBc + so) = *reinterpret_cast<const uint4*>(Bc_ + (size_t)(j0 + r) * 256 + koff + c8);
            *reinterpret_cast<uint4*>((char*)sBg + so) = *reinterpret_cast<const uint4*>(Bg_ + (size_t)(j0 + r) * 256 + koff + c8);
        }
        __syncthreads();

#pragma unroll
        for (int ks = 0; ks < 4; ++ks) {
            uint32_t af[4][4];
#pragma unroll
            for (int mt = 0; mt < 4; ++mt) {
                uint32_t off = swz((uint32_t)((warp_m * 64 + mt * 16 + lm_row) * 128 + (ks * 16 + lm_kh) * 2));
                ldm_x4(af[mt], saA + off);
            }
            uint32_t bcf[2][4], bgf[2][4];
#pragma unroll
            for (int nt2 = 0; nt2 < 2; ++nt2) {
                uint32_t off = swz((uint32_t)((warp_n * 32 + nt2 * 16 + lm_row) * 128 + (ks * 16 + lm_kh) * 2));
                ldm_x4(bcf[nt2], saBc + off);
                ldm_x4(bgf[nt2], saBg + off);
            }
#pragma unroll
            for (int mt = 0; mt < 4; ++mt)
#pragma unroll
                for (int nt = 0; nt < 4; ++nt) {
                    int g2 = nt >> 1, sb = nt & 1;
                    mma16816(accC[mt][nt], af[mt], bcf[g2][sb], bcf[g2][sb + 2]);
                    mma16816(accG[mt][nt], af[mt], bgf[g2][sb], bgf[g2][sb + 2]);
                }
        }
        __syncthreads();
    }

#pragma unroll
    for (int mt = 0; mt < 4; ++mt)
#pragma unroll
        for (int nt = 0; nt < 4; ++nt)
#pragma unroll
            for (int half = 0; half < 2; ++half) {
                int i = i0 + warp_m * 64 + mt * 16 + (lane >> 2) + 8 * half;
                int j = j0 + warp_n * 32 + nt * 8 + (lane & 3) * 2;
                *reinterpret_cast<float2*>(g_C + (size_t)i * FFN_N + j) =
                    make_float2(accC[mt][nt][half * 2 + 0], accC[mt][nt][half * 2 + 1]);
                *reinterpret_cast<float2*>(g_G + (size_t)i * FFN_N + j) =
                    make_float2(accG[mt][nt][half * 2 + 0], accG[mt][nt][half * 2 + 1]);
            }
}

// ---------------- k_epi: fused = g*trop + (1-g)*gelu(C+bc) -> split bf16 ----------------
__global__ __launch_bounds__(256) void k_epi(const float* __restrict__ bc, const float* __restrict__ bg) {
    size_t idx4 = (size_t)blockIdx.x * 256 + threadIdx.x;   // float4 index
    size_t base = idx4 * 4;
    int j = (int)(base & (FFN_N - 1));

    float4 c4 = *reinterpret_cast<const float4*>(g_C + base);
    float4 g4 = *reinterpret_cast<const float4*>(g_G + base);
    float4 t4 = *reinterpret_cast<const float4*>(g_trop + base);
    float4 bc4 = *reinterpret_cast<const float4*>(bc + j);
    float4 bg4 = *reinterpret_cast<const float4*>(bg + j);

    float cv[4] = {c4.x + bc4.x, c4.y + bc4.y, c4.z + bc4.z, c4.w + bc4.w};
    float gv[4] = {g4.x + bg4.x, g4.y + bg4.y, g4.z + bg4.z, g4.w + bg4.w};
    float tv[4] = {t4.x, t4.y, t4.z, t4.w};

    __nv_bfloat16 hb[4], lb[4];
#pragma unroll
    for (int q = 0; q < 4; ++q) {
        float cla = cv[q] * normcdff(cv[q]);
        float gate = 1.0f / (1.0f + expf(-gv[q]));
        float f = gate * tv[q] + (1.0f - gate) * cla;
        hb[q] = __float2bfloat16_rn(f);
        lb[q] = __float2bfloat16_rn(f - __bfloat162float(hb[q]));
    }
    *reinterpret_cast<uint2*>(g_fh + base) = *reinterpret_cast<const uint2*>(hb);
    *reinterpret_cast<uint2*>(g_fl + base) = *reinterpret_cast<const uint2*>(lb);
}

// ---------------- k_d: warp-MMA split-bf16  out = fused @ Wd + bd ----------------
__global__ __launch_bounds__(256, 2) void k_d(const float* __restrict__ bd, float* __restrict__ out) {
    __shared__ __align__(128) __nv_bfloat16 sA[128 * 64];
    __shared__ __align__(128) __nv_bfloat16 sB[128 * 64];

    const int tid = threadIdx.x;
    const int wid = tid >> 5;
    const int lane = tid & 31;
    const int warp_m = wid >> 2;
    const int warp_n = wid & 3;
    const int i0 = blockIdx.x * 128;
    const int n0 = blockIdx.y * 128;

    const uint32_t saA = smem_u32(sA);
    const uint32_t saB = smem_u32(sB);

    float acc[4][4][4];
#pragma unroll
    for (int mt = 0; mt < 4; ++mt)
#pragma unroll
        for (int nt = 0; nt < 4; ++nt)
#pragma unroll
            for (int q = 0; q < 4; ++q) acc[mt][nt][q] = 0.0f;

    const int lm_row = lane & 15;
    const int lm_kh  = (lane >> 4) * 8;

    for (int ch = 0; ch < 48; ++ch) {
        const int term = ch >> 4;
        const int koff = (ch & 15) << 6;
        const __nv_bfloat16* As = (term == 1) ? g_fl  : g_fh;
        const __nv_bfloat16* Bs = (term == 2) ? g_wdl : g_wdh;
#pragma unroll
        for (int t = 0; t < 4; ++t) {
            int idx = tid + (t << 8);
            int r = idx >> 3;
            int c8 = (idx & 7) << 3;
            uint32_t so = swz((uint32_t)(r * 128 + (c8 << 1)));
            *reinterpret_cast<uint4*>((char*)sA + so) = *reinterpret_cast<const uint4*>(As + (size_t)(i0 + r) * FFN_N + koff + c8);
            *reinterpret_cast<uint4*>((char*)sB + so) = *reinterpret_cast<const uint4*>(Bs + (size_t)(n0 + r) * FFN_N + koff + c8);
        }
        __syncthreads();

#pragma unroll
        for (int ks = 0; ks < 4; ++ks) {
            uint32_t af[4][4];
#pragma unroll
            for (int mt = 0; mt < 4; ++mt) {
                uint32_t off = swz((uint32_t)((warp_m * 64 + mt * 16 + lm_row) * 128 + (ks * 16 + lm_kh) * 2));
                ldm_x4(af[mt], saA + off);
            }
            uint32_t bf[2][4];
#pragma unroll
            for (int nt2 = 0; nt2 < 2; ++nt2) {
                uint32_t off = swz((uint32_t)((warp_n * 32 + nt2 * 16 + lm_row) * 128 + (ks * 16 + lm_kh) * 2));
                ldm_x4(bf[nt2], saB + off);
            }
#pragma unroll
            for (int mt = 0; mt < 4; ++mt)
#pragma unroll
                for (int nt = 0; nt < 4; ++nt) {
                    int g2 = nt >> 1, sb = nt & 1;
                    mma16816(acc[mt][nt], af[mt], bf[g2][sb], bf[g2][sb + 2]);
                }
        }
        __syncthreads();
    }

#pragma unroll
    for (int mt = 0; mt < 4; ++mt)
#pragma unroll
        for (int nt = 0; nt < 4; ++nt)
#pragma unroll
            for (int half = 0; half < 2; ++half) {
                int i = i0 + warp_m * 64 + mt * 16 + (lane >> 2) + 8 * half;
                int n = n0 + warp_n * 32 + nt * 8 + (lane & 3) * 2;
                float o0 = acc[mt][nt][half * 2 + 0] + bd[n];
                float o1 = acc[mt][nt][half * 2 + 1] + bd[n + 1];
                *reinterpret_cast<float2*>(out + (size_t)i * D_MOD + n) = make_float2(o0, o1);
            }
}

// ---------------- launch: fork k_cg_mma (tensor) under k_trop (SIMT) ----------------
extern "C" void kernel_launch(void* const* d_in, const int* in_sizes, int n_in,
                              void* d_out, int out_size) {
    const float* x     = (const float*)d_in[0];
    const float* Wt    = (const float*)d_in[1];
    const float* bt    = (const float*)d_in[2];
    const float* slc   = (const float*)d_in[3];
    const float* ofc   = (const float*)d_in[4];
    const float* slv   = (const float*)d_in[5];
    const float* ofv   = (const float*)d_in[6];
    const float* alpha = (const float*)d_in[7];
    const float* Wc    = (const float*)d_in[8];
    const float* bc    = (const float*)d_in[9];
    const float* Wg    = (const float*)d_in[10];
    const float* bg    = (const float*)d_in[11];
    const float* Wd    = (const float*)d_in[12];
    const float* bd    = (const float*)d_in[13];
    float* out = (float*)d_out;

    // fork/join plumbing (created per call; tiny host-side leak, no device allocs)
    cudaStream_t s2;
    cudaEvent_t evF, evJ;
    cudaStreamCreateWithFlags(&s2, cudaStreamNonBlocking);
    cudaEventCreateWithFlags(&evF, cudaEventDisableTiming);
    cudaEventCreateWithFlags(&evJ, cudaEventDisableTiming);

    k_sgate<<<1, 1024>>>(alpha);
    k_split_x<<<(T_TOK * D_MOD / 4) / 256, 256>>>(x);
    k_split_wcg<<<FFN_N, D_MOD>>>(Wc, Wg);
    k_split_wd<<<D_MOD, FFN_N>>>(Wd);

    // fork: tensor-pipe GEMMs on s2, SIMT tropical on main stream
    cudaEventRecord(evF, 0);
    cudaStreamWaitEvent(s2, evF, 0);
    dim3 gcg(T_TOK / 128, FFN_N / 128);
    k_cg_mma<<<gcg, 256, 0, s2>>>();
    cudaEventRecord(evJ, s2);

    dim3 gt(T_TOK / 64, FFN_N / 64);
    k_trop<<<gt, 256>>>(x, Wt, bt, slc, ofc, slv, ofv);

    // join, then epilogue + output GEMM
    cudaStreamWaitEvent(0, evJ, 0);
    k_epi<<<(T_TOK * FFN_N / 4) / 256, 256>>>(bc, bg);

    dim3 gd(T_TOK / 128, D_MOD / 128);
    k_d<<<gd, 256>>>(bd, out);
}

// round 7
// speedup vs baseline: 1.6183x; 1.2278x over previous
#include <cuda_runtime.h>
#include <cuda_bf16.h>
#include <cstdint>
#include <cmath>

#define T_TOK 32768
#define D_MOD 256
#define FFN_N 1024

// ---------------- scratch ----------------
__device__ float g_trop[(size_t)T_TOK * FFN_N];
__device__ float g_C[(size_t)T_TOK * FFN_N];
__device__ float g_G[(size_t)T_TOK * FFN_N];
__device__ float g_sgate[FFN_N];
__device__ __nv_bfloat16 g_xh[(size_t)T_TOK * D_MOD];
__device__ __nv_bfloat16 g_xl[(size_t)T_TOK * D_MOD];
__device__ __nv_bfloat16 g_wch[FFN_N * D_MOD];
__device__ __nv_bfloat16 g_wcl[FFN_N * D_MOD];
__device__ __nv_bfloat16 g_wgh[FFN_N * D_MOD];
__device__ __nv_bfloat16 g_wgl[FFN_N * D_MOD];
__device__ __nv_bfloat16 g_wdh[D_MOD * FFN_N];
__device__ __nv_bfloat16 g_wdl[D_MOD * FFN_N];
__device__ __nv_bfloat16 g_fh[(size_t)T_TOK * FFN_N];
__device__ __nv_bfloat16 g_fl[(size_t)T_TOK * FFN_N];

// ---------------- helpers ----------------
__device__ __forceinline__ uint32_t smem_u32(const void* p) {
    uint32_t a;
    asm("{ .reg .u64 t; cvta.to.shared.u64 t, %1; cvt.u32.u64 %0, t; }" : "=r"(a) : "l"(p));
    return a;
}
__device__ __forceinline__ uint32_t swz(uint32_t off) { return off ^ ((off >> 3) & 0x70); }

__device__ __forceinline__ void ldm_x4(uint32_t* r, uint32_t addr) {
    asm volatile("ldmatrix.sync.aligned.m8n8.x4.shared.b16 {%0,%1,%2,%3}, [%4];"
                 : "=r"(r[0]), "=r"(r[1]), "=r"(r[2]), "=r"(r[3]) : "r"(addr));
}
__device__ __forceinline__ void mma16816(float* c, const uint32_t* a, uint32_t b0, uint32_t b1) {
    asm volatile("mma.sync.aligned.m16n8k16.row.col.f32.bf16.bf16.f32 "
                 "{%0,%1,%2,%3}, {%4,%5,%6,%7}, {%8,%9}, {%0,%1,%2,%3};"
                 : "+f"(c[0]), "+f"(c[1]), "+f"(c[2]), "+f"(c[3])
                 : "r"(a[0]), "r"(a[1]), "r"(a[2]), "r"(a[3]), "r"(b0), "r"(b1));
}
// packed f32x2 add with scalar in/out (lets ptxas alias register pairs)
__device__ __forceinline__ void add2s(float& olo, float& ohi, float alo, float ahi, float blo, float bhi) {
    asm("{ .reg .b64 pa, pb, pd;\n\t"
        "mov.b64 pa, {%2,%3};\n\t"
        "mov.b64 pb, {%4,%5};\n\t"
        "add.rn.f32x2 pd, pa, pb;\n\t"
        "mov.b64 {%0,%1}, pd; }"
        : "=f"(olo), "=f"(ohi) : "f"(alo), "f"(ahi), "f"(blo), "f"(bhi));
}
__device__ __forceinline__ void cp16(uint32_t s, const void* g) {
    asm volatile("{ .reg .u64 gp; cvta.to.global.u64 gp, %1; cp.async.cg.shared.global [%0], [gp], 16; }"
                 :: "r"(s), "l"(g));
}
#define CP_COMMIT() asm volatile("cp.async.commit_group;" ::: "memory")
#define CP_WAIT1()  asm volatile("cp.async.wait_group 1;" ::: "memory")
#define CP_WAIT0()  asm volatile("cp.async.wait_group 0;" ::: "memory")

// ---------------- preps ----------------
__global__ void k_sgate(const float* __restrict__ alpha) {
    int j = threadIdx.x;
    g_sgate[j] = 1.0f / (1.0f + expf(-alpha[j]));
}
__global__ void k_split_x(const float* __restrict__ x) {
    size_t idx = (size_t)blockIdx.x * 256 + threadIdx.x;
    float4 v = reinterpret_cast<const float4*>(x)[idx];
    float f[4] = {v.x, v.y, v.z, v.w};
    __nv_bfloat16 h[4], l[4];
#pragma unroll
    for (int q = 0; q < 4; ++q) {
        h[q] = __float2bfloat16_rn(f[q]);
        l[q] = __float2bfloat16_rn(f[q] - __bfloat162float(h[q]));
    }
    __nv_bfloat162* ph = reinterpret_cast<__nv_bfloat162*>(g_xh) + idx * 2;
    __nv_bfloat162* pl = reinterpret_cast<__nv_bfloat162*>(g_xl) + idx * 2;
    ph[0] = __nv_bfloat162(h[0], h[1]); ph[1] = __nv_bfloat162(h[2], h[3]);
    pl[0] = __nv_bfloat162(l[0], l[1]); pl[1] = __nv_bfloat162(l[2], l[3]);
}
__global__ void k_split_wcg(const float* __restrict__ Wc, const float* __restrict__ Wg) {
    int j = blockIdx.x;
    int d = threadIdx.x;
    float c = Wc[(size_t)d * FFN_N + j];
    __nv_bfloat16 ch = __float2bfloat16_rn(c);
    g_wch[(size_t)j * D_MOD + d] = ch;
    g_wcl[(size_t)j * D_MOD + d] = __float2bfloat16_rn(c - __bfloat162float(ch));
    float g = Wg[(size_t)d * FFN_N + j];
    __nv_bfloat16 gh = __float2bfloat16_rn(g);
    g_wgh[(size_t)j * D_MOD + d] = gh;
    g_wgl[(size_t)j * D_MOD + d] = __float2bfloat16_rn(g - __bfloat162float(gh));
}
__global__ void k_split_wd(const float* __restrict__ Wd) {
    int n = blockIdx.x;
    int k = threadIdx.x;
    float w = Wd[(size_t)k * D_MOD + n];
    __nv_bfloat16 wh = __float2bfloat16_rn(w);
    g_wdh[(size_t)n * FFN_N + k] = wh;
    g_wdl[(size_t)n * FFN_N + k] = __float2bfloat16_rn(w - __bfloat162float(wh));
}

// ---------------- tropical kernel: m8n4, ADD2 + 2x FMNMX ----------------
__global__ __launch_bounds__(256, 2) void k_trop(
    const float* __restrict__ x, const float* __restrict__ Wt, const float* __restrict__ bt,
    const float* __restrict__ slc, const float* __restrict__ ofc,
    const float* __restrict__ slv, const float* __restrict__ ofv)
{
    __shared__ __align__(16) float2 xs2[16][130];
    __shared__ __align__(16) float2 ws2[16][66];

    const int tid = threadIdx.x;
    const int tx = tid & 15;
    const int ty = tid >> 4;
    const int i0 = blockIdx.x * 128;
    const int j0 = blockIdx.y * 64;

    // packed accumulators: mlo/mhi per (a,b); folded at epilogue
    float mlo[8][4], mhi[8][4];
#pragma unroll
    for (int a = 0; a < 8; ++a)
#pragma unroll
        for (int b = 0; b < 4; ++b) { mlo[a][b] = -3.402823466e38f; mhi[a][b] = -3.402823466e38f; }

    for (int kc = 0; kc < 256; kc += 32) {
#pragma unroll
        for (int t = 0; t < 4; ++t) {
            int idx = tid + (t << 8);
            int r  = idx >> 3;               // 0..127
            int k2 = (idx & 7) << 1;
            float4 v = *reinterpret_cast<const float4*>(x + (size_t)(i0 + r) * 256 + kc + (k2 << 1));
            xs2[k2][r]     = make_float2(v.x, v.y);
            xs2[k2 + 1][r] = make_float2(v.z, v.w);
        }
#pragma unroll
        for (int t = 0; t < 2; ++t) {
            int idx = tid + (t << 8);
            int r  = idx >> 3;               // 0..63
            int k2 = (idx & 7) << 1;
            float4 w = *reinterpret_cast<const float4*>(Wt + (size_t)(j0 + r) * 256 + kc + (k2 << 1));
            ws2[k2][r]     = make_float2(w.x, w.y);
            ws2[k2 + 1][r] = make_float2(w.z, w.w);
        }
        __syncthreads();

#pragma unroll 4
        for (int k2 = 0; k2 < 16; ++k2) {
            float2 xp[8], wp[4];
#pragma unroll
            for (int q = 0; q < 2; ++q) {
                float4 u0 = *reinterpret_cast<const float4*>(&xs2[k2][(ty << 3) + (q << 2)]);
                float4 u1 = *reinterpret_cast<const float4*>(&xs2[k2][(ty << 3) + (q << 2) + 2]);
                xp[q * 4 + 0] = make_float2(u0.x, u0.y);
                xp[q * 4 + 1] = make_float2(u0.z, u0.w);
                xp[q * 4 + 2] = make_float2(u1.x, u1.y);
                xp[q * 4 + 3] = make_float2(u1.z, u1.w);
            }
            {
                float4 u0 = *reinterpret_cast<const float4*>(&ws2[k2][tx << 2]);
                float4 u1 = *reinterpret_cast<const float4*>(&ws2[k2][(tx << 2) + 2]);
                wp[0] = make_float2(u0.x, u0.y);
                wp[1] = make_float2(u0.z, u0.w);
                wp[2] = make_float2(u1.x, u1.y);
                wp[3] = make_float2(u1.z, u1.w);
            }
#pragma unroll
            for (int a = 0; a < 8; ++a)
#pragma unroll
                for (int b = 0; b < 4; ++b) {
                    float tl, th;
                    add2s(tl, th, xp[a].x, xp[a].y, wp[b].x, wp[b].y);
                    mlo[a][b] = fmaxf(mlo[a][b], tl);
                    mhi[a][b] = fmaxf(mhi[a][b], th);
                }
        }
        __syncthreads();
    }

    float res[8][4];
#pragma unroll
    for (int b = 0; b < 4; ++b) {
        int j = j0 + (tx << 2) + b;
        float btj = bt[j];
        float sj  = g_sgate[j];
        float4 s0 = *reinterpret_cast<const float4*>(slc + j * 8);
        float4 s1 = *reinterpret_cast<const float4*>(slc + j * 8 + 4);
        float4 o0 = *reinterpret_cast<const float4*>(ofc + j * 8);
        float4 o1 = *reinterpret_cast<const float4*>(ofc + j * 8 + 4);
        float4 v0 = *reinterpret_cast<const float4*>(slv + j * 8);
        float4 v1 = *reinterpret_cast<const float4*>(slv + j * 8 + 4);
        float4 w0 = *reinterpret_cast<const float4*>(ofv + j * 8);
        float4 w1 = *reinterpret_cast<const float4*>(ofv + j * 8 + 4);
#pragma unroll
        for (int a = 0; a < 8; ++a) {
            float t = fmaxf(mlo[a][b], mhi[a][b]) + btj;
            float cvx = fmaf(t, s0.x, o0.x);
            cvx = fmaxf(cvx, fmaf(t, s0.y, o0.y));
            cvx = fmaxf(cvx, fmaf(t, s0.z, o0.z));
            cvx = fmaxf(cvx, fmaf(t, s0.w, o0.w));
            cvx = fmaxf(cvx, fmaf(t, s1.x, o1.x));
            cvx = fmaxf(cvx, fmaf(t, s1.y, o1.y));
            cvx = fmaxf(cvx, fmaf(t, s1.z, o1.z));
            cvx = fmaxf(cvx, fmaf(t, s1.w, o1.w));
            float ccv = fmaf(t, v0.x, w0.x);
            ccv = fminf(ccv, fmaf(t, v0.y, w0.y));
            ccv = fminf(ccv, fmaf(t, v0.z, w0.z));
            ccv = fminf(ccv, fmaf(t, v0.w, w0.w));
            ccv = fminf(ccv, fmaf(t, v1.x, w1.x));
            ccv = fminf(ccv, fmaf(t, v1.y, w1.y));
            ccv = fminf(ccv, fmaf(t, v1.z, w1.z));
            ccv = fminf(ccv, fmaf(t, v1.w, w1.w));
            res[a][b] = sj * cvx + (1.0f - sj) * ccv;
        }
    }
#pragma unroll
    for (int a = 0; a < 8; ++a) {
        float4 st = make_float4(res[a][0], res[a][1], res[a][2], res[a][3]);
        *reinterpret_cast<float4*>(g_trop + (size_t)(i0 + (ty << 3) + a) * FFN_N + j0 + (tx << 2)) = st;
    }
}

// ---------------- k_cg_mma: double-buffered cp.async, C & G GEMMs ----------------
#define CG_BUF 49152
#define CG_SMEM (2 * CG_BUF)
__global__ __launch_bounds__(256, 1) void k_cg_mma() {
    extern __shared__ char dsm[];
    const uint32_t sb = smem_u32(dsm);

    const int tid = threadIdx.x;
    const int wid = tid >> 5;
    const int lane = tid & 31;
    const int warp_m = wid >> 2;
    const int warp_n = wid & 3;
    const int i0 = blockIdx.x * 128;
    const int j0 = blockIdx.y * 128;

    float accC[4][4][4];
    float accG[4][4][4];
#pragma unroll
    for (int mt = 0; mt < 4; ++mt)
#pragma unroll
        for (int nt = 0; nt < 4; ++nt)
#pragma unroll
            for (int q = 0; q < 4; ++q) { accC[mt][nt][q] = 0.0f; accG[mt][nt][q] = 0.0f; }

    const int lm_row = lane & 15;
    const int lm_kh  = (lane >> 4) * 8;

    auto issue = [&](int ch) {
        const int term = ch >> 2;
        const int koff = (ch & 3) << 6;
        const __nv_bfloat16* As  = (term == 1) ? g_xl  : g_xh;
        const __nv_bfloat16* Bc_ = (term == 2) ? g_wcl : g_wch;
        const __nv_bfloat16* Bg_ = (term == 2) ? g_wgl : g_wgh;
        const uint32_t buf = sb + (ch & 1) * CG_BUF;
#pragma unroll
        for (int t = 0; t < 4; ++t) {
            int idx = tid + (t << 8);
            int r = idx >> 3;
            int c8 = (idx & 7) << 3;
            uint32_t so = swz((uint32_t)(r * 128 + (c8 << 1)));
            cp16(buf + so,          As  + (size_t)(i0 + r) * 256 + koff + c8);
            cp16(buf + 16384 + so,  Bc_ + (size_t)(j0 + r) * 256 + koff + c8);
            cp16(buf + 32768 + so,  Bg_ + (size_t)(j0 + r) * 256 + koff + c8);
        }
        CP_COMMIT();
    };

    issue(0);
    for (int ch = 0; ch < 12; ++ch) {
        if (ch + 1 < 12) { issue(ch + 1); CP_WAIT1(); } else { CP_WAIT0(); }
        __syncthreads();
        const uint32_t buf = sb + (ch & 1) * CG_BUF;
#pragma unroll
        for (int ks = 0; ks < 4; ++ks) {
            uint32_t af[4][4];
#pragma unroll
            for (int mt = 0; mt < 4; ++mt) {
                uint32_t off = swz((uint32_t)((warp_m * 64 + mt * 16 + lm_row) * 128 + (ks * 16 + lm_kh) * 2));
                ldm_x4(af[mt], buf + off);
            }
            uint32_t bcf[2][4], bgf[2][4];
#pragma unroll
            for (int nt2 = 0; nt2 < 2; ++nt2) {
                uint32_t off = swz((uint32_t)((warp_n * 32 + nt2 * 16 + lm_row) * 128 + (ks * 16 + lm_kh) * 2));
                ldm_x4(bcf[nt2], buf + 16384 + off);
                ldm_x4(bgf[nt2], buf + 32768 + off);
            }
#pragma unroll
            for (int mt = 0; mt < 4; ++mt)
#pragma unroll
                for (int nt = 0; nt < 4; ++nt) {
                    int g2 = nt >> 1, sbn = nt & 1;
                    mma16816(accC[mt][nt], af[mt], bcf[g2][sbn], bcf[g2][sbn + 2]);
                    mma16816(accG[mt][nt], af[mt], bgf[g2][sbn], bgf[g2][sbn + 2]);
                }
        }
        __syncthreads();
    }

#pragma unroll
    for (int mt = 0; mt < 4; ++mt)
#pragma unroll
        for (int nt = 0; nt < 4; ++nt)
#pragma unroll
            for (int half = 0; half < 2; ++half) {
                int i = i0 + warp_m * 64 + mt * 16 + (lane >> 2) + 8 * half;
                int j = j0 + warp_n * 32 + nt * 8 + (lane & 3) * 2;
                *reinterpret_cast<float2*>(g_C + (size_t)i * FFN_N + j) =
                    make_float2(accC[mt][nt][half * 2 + 0], accC[mt][nt][half * 2 + 1]);
                *reinterpret_cast<float2*>(g_G + (size_t)i * FFN_N + j) =
                    make_float2(accG[mt][nt][half * 2 + 0], accG[mt][nt][half * 2 + 1]);
            }
}

// ---------------- k_epi ----------------
__global__ __launch_bounds__(256) void k_epi(const float* __restrict__ bc, const float* __restrict__ bg) {
    size_t idx4 = (size_t)blockIdx.x * 256 + threadIdx.x;
    size_t base = idx4 * 4;
    int j = (int)(base & (FFN_N - 1));

    float4 c4 = *reinterpret_cast<const float4*>(g_C + base);
    float4 g4 = *reinterpret_cast<const float4*>(g_G + base);
    float4 t4 = *reinterpret_cast<const float4*>(g_trop + base);
    float4 bc4 = *reinterpret_cast<const float4*>(bc + j);
    float4 bg4 = *reinterpret_cast<const float4*>(bg + j);

    float cv[4] = {c4.x + bc4.x, c4.y + bc4.y, c4.z + bc4.z, c4.w + bc4.w};
    float gv[4] = {g4.x + bg4.x, g4.y + bg4.y, g4.z + bg4.z, g4.w + bg4.w};
    float tv[4] = {t4.x, t4.y, t4.z, t4.w};

    __nv_bfloat16 hb[4], lb[4];
#pragma unroll
    for (int q = 0; q < 4; ++q) {
        float cla = cv[q] * normcdff(cv[q]);
        float gate = 1.0f / (1.0f + expf(-gv[q]));
        float f = gate * tv[q] + (1.0f - gate) * cla;
        hb[q] = __float2bfloat16_rn(f);
        lb[q] = __float2bfloat16_rn(f - __bfloat162float(hb[q]));
    }
    *reinterpret_cast<uint2*>(g_fh + base) = *reinterpret_cast<const uint2*>(hb);
    *reinterpret_cast<uint2*>(g_fl + base) = *reinterpret_cast<const uint2*>(lb);
}

// ---------------- k_d: double-buffered cp.async ----------------
#define KD_BUF 32768
#define KD_SMEM (2 * KD_BUF)
__global__ __launch_bounds__(256, 2) void k_d(const float* __restrict__ bd, float* __restrict__ out) {
    extern __shared__ char dsm[];
    const uint32_t sb = smem_u32(dsm);

    const int tid = threadIdx.x;
    const int wid = tid >> 5;
    const int lane = tid & 31;
    const int warp_m = wid >> 2;
    const int warp_n = wid & 3;
    const int i0 = blockIdx.x * 128;
    const int n0 = blockIdx.y * 128;

    float acc[4][4][4];
#pragma unroll
    for (int mt = 0; mt < 4; ++mt)
#pragma unroll
        for (int nt = 0; nt < 4; ++nt)
#pragma unroll
            for (int q = 0; q < 4; ++q) acc[mt][nt][q] = 0.0f;

    const int lm_row = lane & 15;
    const int lm_kh  = (lane >> 4) * 8;

    auto issue = [&](int ch) {
        const int term = ch >> 4;
        const int koff = (ch & 15) << 6;
        const __nv_bfloat16* As = (term == 1) ? g_fl  : g_fh;
        const __nv_bfloat16* Bs = (term == 2) ? g_wdl : g_wdh;
        const uint32_t buf = sb + (ch & 1) * KD_BUF;
#pragma unroll
        for (int t = 0; t < 4; ++t) {
            int idx = tid + (t << 8);
            int r = idx >> 3;
            int c8 = (idx & 7) << 3;
            uint32_t so = swz((uint32_t)(r * 128 + (c8 << 1)));
            cp16(buf + so,         As + (size_t)(i0 + r) * FFN_N + koff + c8);
            cp16(buf + 16384 + so, Bs + (size_t)(n0 + r) * FFN_N + koff + c8);
        }
        CP_COMMIT();
    };

    issue(0);
    for (int ch = 0; ch < 48; ++ch) {
        if (ch + 1 < 48) { issue(ch + 1); CP_WAIT1(); } else { CP_WAIT0(); }
        __syncthreads();
        const uint32_t buf = sb + (ch & 1) * KD_BUF;
#pragma unroll
        for (int ks = 0; ks < 4; ++ks) {
            uint32_t af[4][4];
#pragma unroll
            for (int mt = 0; mt < 4; ++mt) {
                uint32_t off = swz((uint32_t)((warp_m * 64 + mt * 16 + lm_row) * 128 + (ks * 16 + lm_kh) * 2));
                ldm_x4(af[mt], buf + off);
            }
            uint32_t bf[2][4];
#pragma unroll
            for (int nt2 = 0; nt2 < 2; ++nt2) {
                uint32_t off = swz((uint32_t)((warp_n * 32 + nt2 * 16 + lm_row) * 128 + (ks * 16 + lm_kh) * 2));
                ldm_x4(bf[nt2], buf + 16384 + off);
            }
#pragma unroll
            for (int mt = 0; mt < 4; ++mt)
#pragma unroll
                for (int nt = 0; nt < 4; ++nt) {
                    int g2 = nt >> 1, sbn = nt & 1;
                    mma16816(acc[mt][nt], af[mt], bf[g2][sbn], bf[g2][sbn + 2]);
                }
        }
        __syncthreads();
    }

#pragma unroll
    for (int mt = 0; mt < 4; ++mt)
#pragma unroll
        for (int nt = 0; nt < 4; ++nt)
#pragma unroll
            for (int half = 0; half < 2; ++half) {
                int i = i0 + warp_m * 64 + mt * 16 + (lane >> 2) + 8 * half;
                int n = n0 + warp_n * 32 + nt * 8 + (lane & 3) * 2;
                float o0 = acc[mt][nt][half * 2 + 0] + bd[n];
                float o1 = acc[mt][nt][half * 2 + 1] + bd[n + 1];
                *reinterpret_cast<float2*>(out + (size_t)i * D_MOD + n) = make_float2(o0, o1);
            }
}

// ---------------- launch ----------------
extern "C" void kernel_launch(void* const* d_in, const int* in_sizes, int n_in,
                              void* d_out, int out_size) {
    const float* x     = (const float*)d_in[0];
    const float* Wt    = (const float*)d_in[1];
    const float* bt    = (const float*)d_in[2];
    const float* slc   = (const float*)d_in[3];
    const float* ofc   = (const float*)d_in[4];
    const float* slv   = (const float*)d_in[5];
    const float* ofv   = (const float*)d_in[6];
    const float* alpha = (const float*)d_in[7];
    const float* Wc    = (const float*)d_in[8];
    const float* bc    = (const float*)d_in[9];
    const float* Wg    = (const float*)d_in[10];
    const float* bg    = (const float*)d_in[11];
    const float* Wd    = (const float*)d_in[12];
    const float* bd    = (const float*)d_in[13];
    float* out = (float*)d_out;

    cudaFuncSetAttribute(k_cg_mma, cudaFuncAttributeMaxDynamicSharedMemorySize, CG_SMEM);
    cudaFuncSetAttribute(k_d,      cudaFuncAttributeMaxDynamicSharedMemorySize, KD_SMEM);

    cudaStream_t s2;
    cudaEvent_t evF, evJ;
    cudaStreamCreateWithFlags(&s2, cudaStreamNonBlocking);
    cudaEventCreateWithFlags(&evF, cudaEventDisableTiming);
    cudaEventCreateWithFlags(&evJ, cudaEventDisableTiming);

    k_sgate<<<1, 1024>>>(alpha);
    k_split_x<<<(T_TOK * D_MOD / 4) / 256, 256>>>(x);
    k_split_wcg<<<FFN_N, D_MOD>>>(Wc, Wg);
    k_split_wd<<<D_MOD, FFN_N>>>(Wd);

    cudaEventRecord(evF, 0);
    cudaStreamWaitEvent(s2, evF, 0);
    dim3 gcg(T_TOK / 128, FFN_N / 128);
    k_cg_mma<<<gcg, 256, CG_SMEM, s2>>>();
    cudaEventRecord(evJ, s2);

    dim3 gt(T_TOK / 128, FFN_N / 64);
    k_trop<<<gt, 256>>>(x, Wt, bt, slc, ofc, slv, ofv);

    cudaStreamWaitEvent(0, evJ, 0);
    k_epi<<<(T_TOK * FFN_N / 4) / 256, 256>>>(bc, bg);

    dim3 gd(T_TOK / 128, D_MOD / 128);
    k_d<<<gd, 256, KD_SMEM>>>(bd, out);
}